// round 10
// baseline (speedup 1.0000x reference)
#include <cuda_runtime.h>
#include <cuda_fp16.h>
#include <cstdint>
#include <stdint.h>

#define STU_NUM  100000
#define PROB_NUM 20000
#define KNOW_NUM 128
#define DIM      128
#define BATCH    8192
#define HIDDEN   512
#define KOFF     (STU_NUM + PROB_NUM)

// ---------------- intermediate buffers (L2-resident) ----------------
__device__ __align__(16) __half g_S [BATCH * KNOW_NUM];         // 2 MB
__device__ __align__(16) __half g_H1[BATCH * HIDDEN];           // 8 MB
__device__ __align__(16) __half g_H2[BATCH * (HIDDEN / 2)];     // 4 MB
__device__ __align__(16) __half g_H3[BATCH * (HIDDEN / 4)];     // 2 MB
__device__ __align__(16) __half g_W1h[DIM * HIDDEN];
__device__ __align__(16) __half g_W2h[HIDDEN * (HIDDEN / 2)];
__device__ __align__(16) __half g_W3h[(HIDDEN / 2) * (HIDDEN / 4)];

__device__ __forceinline__ float sigmoidf_(float x) {
    return 1.0f / (1.0f + __expf(-x));
}
__device__ __forceinline__ float tanhf_(float x) {
    return 1.0f - 2.0f / (__expf(2.0f * x) + 1.0f);
}

// ---------------- PTX helpers ----------------
__device__ __forceinline__ uint32_t s2u(const void* p) {
    return (uint32_t)__cvta_generic_to_shared(p);
}
__device__ __forceinline__ void ldmA(uint32_t addr, uint32_t& a0, uint32_t& a1,
                                     uint32_t& a2, uint32_t& a3) {
    asm volatile("ldmatrix.sync.aligned.m8n8.x4.shared.b16 {%0,%1,%2,%3}, [%4];"
                 : "=r"(a0), "=r"(a1), "=r"(a2), "=r"(a3) : "r"(addr));
}
__device__ __forceinline__ void ldmBT(uint32_t addr, uint32_t& b0, uint32_t& b1) {
    asm volatile("ldmatrix.sync.aligned.m8n8.x2.trans.shared.b16 {%0,%1}, [%2];"
                 : "=r"(b0), "=r"(b1) : "r"(addr));
}
// non-transposed x2 (for B stored [N,K] row-major)
__device__ __forceinline__ void ldmBN(uint32_t addr, uint32_t& b0, uint32_t& b1) {
    asm volatile("ldmatrix.sync.aligned.m8n8.x2.shared.b16 {%0,%1}, [%2];"
                 : "=r"(b0), "=r"(b1) : "r"(addr));
}
__device__ __forceinline__ void mma16816(float* d, uint32_t a0, uint32_t a1,
                                         uint32_t a2, uint32_t a3,
                                         uint32_t b0, uint32_t b1) {
    asm volatile("mma.sync.aligned.m16n8k16.row.col.f32.f16.f16.f32 "
                 "{%0,%1,%2,%3}, {%4,%5,%6,%7}, {%8,%9}, {%0,%1,%2,%3};"
                 : "+f"(d[0]), "+f"(d[1]), "+f"(d[2]), "+f"(d[3])
                 : "r"(a0), "r"(a1), "r"(a2), "r"(a3), "r"(b0), "r"(b1));
}
__device__ __forceinline__ void cpasync16(uint32_t saddr, const void* g) {
    asm volatile("cp.async.cg.shared.global [%0], [%1], 16;" :: "r"(saddr), "l"(g));
}
__device__ __forceinline__ uint32_t pk2(float a, float b) {
    __half2 h = __floats2half2_rn(a, b);
    return *(uint32_t*)&h;
}

// ================= fused head: gather + 2x GEMM vs K + sigmoid-diff =========
// Block: 128 batch rows x 64 knowledge cols. grid (2, 64), 256 threads.
// smem: A 128x128 half (32KB, XOR-swizzled), B 64x128 half [N,K] (16KB).
// Pass 0: A = z[sid]*w_stat  -> accS.  Pass 1: A = z[eid]*w_kdiff -> accK.
// Epilogue: S = kp * (sig(accS+bs) - sig(accK+bk)), written fp16.
__global__ __launch_bounds__(256) void head_k(const float* __restrict__ z,
                                              const int* __restrict__ sid,
                                              const int* __restrict__ eid,
                                              const float* __restrict__ w_stat,
                                              const float* __restrict__ w_kdiff,
                                              const float* __restrict__ kp,
                                              const float* __restrict__ bs_p,
                                              const float* __restrict__ bk_p)
{
    __shared__ __align__(16) uint4 a_sm[128 * 16];   // 32 KB
    __shared__ __align__(16) uint4 b_sm[64 * 16];    // 16 KB

    const int tid  = threadIdx.x;
    const int lane = tid & 31;
    const int warp = tid >> 5;
    const int wm   = (warp >> 1) * 32;   // 4 m-groups
    const int wn   = (warp & 1) * 32;    // 2 n-groups
    const int bm   = blockIdx.y * 128;
    const int bn   = blockIdx.x * 64;

    // ---- B fill: knowledge rows [n][k], swizzled 16B units ----
    {
        int n  = tid >> 2;               // 0..63
        int u0 = (tid & 3) * 4;
        const float* src = z + (size_t)(KOFF + bn + n) * DIM;
        #pragma unroll
        for (int q = 0; q < 4; q++) {
            int u = u0 + q;
            float4 f0 = *(const float4*)(src + u * 8);
            float4 f1 = *(const float4*)(src + u * 8 + 4);
            uint4 v;
            v.x = pk2(f0.x, f0.y); v.y = pk2(f0.z, f0.w);
            v.z = pk2(f1.x, f1.y); v.w = pk2(f1.z, f1.w);
            b_sm[n * 16 + (u ^ (n & 7))] = v;
        }
    }

    float accS[2][4][4], accK[2][4][4];
    #pragma unroll
    for (int mi = 0; mi < 2; mi++)
        #pragma unroll
        for (int ni = 0; ni < 4; ni++)
            #pragma unroll
            for (int q = 0; q < 4; q++) { accS[mi][ni][q] = 0.0f; accK[mi][ni][q] = 0.0f; }

    auto fill_A = [&](const int* __restrict__ ids, const float* __restrict__ w) {
        int r  = tid >> 1;               // 0..127
        int u0 = (tid & 1) * 8;
        const float* src = z + (size_t)ids[bm + r] * DIM;
        #pragma unroll
        for (int q = 0; q < 8; q++) {
            int u = u0 + q;
            float4 f0 = *(const float4*)(src + u * 8);
            float4 f1 = *(const float4*)(src + u * 8 + 4);
            float4 w0 = *(const float4*)(w + u * 8);
            float4 w1 = *(const float4*)(w + u * 8 + 4);
            uint4 v;
            v.x = pk2(f0.x * w0.x, f0.y * w0.y);
            v.y = pk2(f0.z * w0.z, f0.w * w0.w);
            v.z = pk2(f1.x * w1.x, f1.y * w1.y);
            v.w = pk2(f1.z * w1.z, f1.w * w1.w);
            a_sm[r * 16 + (u ^ (r & 7))] = v;
        }
    };

    auto mma_pass = [&](float (&acc)[2][4][4]) {
        #pragma unroll
        for (int ks = 0; ks < 8; ks++) {
            uint32_t a[2][4], b[4][2];
            #pragma unroll
            for (int mi = 0; mi < 2; mi++) {
                int r = wm + mi * 16 + (lane & 15);
                int u = ks * 2 + (lane >> 4);
                ldmA(s2u(&a_sm[r * 16 + (u ^ (r & 7))]),
                     a[mi][0], a[mi][1], a[mi][2], a[mi][3]);
            }
            #pragma unroll
            for (int ni = 0; ni < 4; ni++) {
                int n = wn + ni * 8 + (lane & 7);
                int u = ks * 2 + ((lane >> 3) & 1);
                ldmBN(s2u(&b_sm[n * 16 + (u ^ (n & 7))]), b[ni][0], b[ni][1]);
            }
            #pragma unroll
            for (int mi = 0; mi < 2; mi++)
                #pragma unroll
                for (int ni = 0; ni < 4; ni++)
                    mma16816(acc[mi][ni], a[mi][0], a[mi][1], a[mi][2], a[mi][3],
                             b[ni][0], b[ni][1]);
        }
    };

    fill_A(sid, w_stat);
    __syncthreads();
    mma_pass(accS);
    __syncthreads();          // A reused
    fill_A(eid, w_kdiff);
    __syncthreads();
    mma_pass(accK);

    // ---- epilogue: combine in-register ----
    const float bs = *bs_p, bk = *bk_p;
    #pragma unroll
    for (int mi = 0; mi < 2; mi++) {
        const int r  = wm + mi * 16 + (lane >> 2);
        const int g0 = bm + r, g1 = g0 + 8;
        #pragma unroll
        for (int ni = 0; ni < 4; ni++) {
            const int c  = bn + wn + ni * 8 + (lane & 3) * 2;
            float2 kp0 = *(const float2*)(kp + (size_t)g0 * KNOW_NUM + c);
            float2 kp1 = *(const float2*)(kp + (size_t)g1 * KNOW_NUM + c);
            float s0 = kp0.x * (sigmoidf_(accS[mi][ni][0] + bs) - sigmoidf_(accK[mi][ni][0] + bk));
            float s1 = kp0.y * (sigmoidf_(accS[mi][ni][1] + bs) - sigmoidf_(accK[mi][ni][1] + bk));
            float s2 = kp1.x * (sigmoidf_(accS[mi][ni][2] + bs) - sigmoidf_(accK[mi][ni][2] + bk));
            float s3 = kp1.y * (sigmoidf_(accS[mi][ni][3] + bs) - sigmoidf_(accK[mi][ni][3] + bk));
            *(__half2*)(g_S + (size_t)g0 * KNOW_NUM + c) = __floats2half2_rn(s0, s1);
            *(__half2*)(g_S + (size_t)g1 * KNOW_NUM + c) = __floats2half2_rn(s2, s3);
        }
    }
}

// ---------------- weight fp32 -> fp16 conversion ----------------
__global__ __launch_bounds__(256) void prep_weights(const float* __restrict__ W1,
                                                    const float* __restrict__ W2,
                                                    const float* __restrict__ W3)
{
    int i = blockIdx.x * blockDim.x + threadIdx.x;
    const float* src; __half* dst; int off;
    if (i < 16384)      { src = W1; dst = g_W1h; off = i; }
    else if (i < 49152) { src = W2; dst = g_W2h; off = i - 16384; }
    else                { src = W3; dst = g_W3h; off = i - 49152; }
    float4 v = ((const float4*)src)[off];
    __half2* d = (__half2*)(dst + (size_t)off * 4);
    d[0] = __floats2half2_rn(v.x, v.y);
    d[1] = __floats2half2_rn(v.z, v.w);
}

// ---------------- fp16 MLP GEMM: BM=128 BN=64 BK=32, 256 thr, warp tile 32x32 -
template <int EPI_TANH>
__device__ __forceinline__ void hgemm_body(const __half* __restrict__ A,
                                           const __half* __restrict__ B,
                                           const float* __restrict__ bias,
                                           __half* __restrict__ C,
                                           int M, int N, int K)
{
    constexpr int BM = 128, BN = 64, BK = 32;
    constexpr int LDA = 40, LDB = 72;
    __shared__ __align__(16) __half As[2][BM * LDA];
    __shared__ __align__(16) __half Bs[2][BK * LDB];

    const int tid  = threadIdx.x;
    const int lane = tid & 31;
    const int warp = tid >> 5;
    const int wm   = (warp >> 1) * 32;
    const int wn   = (warp & 1) * 32;
    const int bm   = blockIdx.y * BM;
    const int bn   = blockIdx.x * BN;

    auto load_tile = [&](int buf, int k0) {
        #pragma unroll
        for (int j = 0; j < 2; j++) {                  // A: 512 x 16B
            int id = j * 256 + tid; int r = id >> 2, c = (id & 3) * 8;
            cpasync16(s2u(&As[buf][r * LDA + c]), A + (size_t)(bm + r) * K + k0 + c);
        }
        {                                              // B: 256 x 16B
            int r = tid >> 3, c = (tid & 7) * 8;
            cpasync16(s2u(&Bs[buf][r * LDB + c]), B + (size_t)(k0 + r) * N + bn + c);
        }
        asm volatile("cp.async.commit_group;");
    };

    float acc[2][4][4];
    #pragma unroll
    for (int mi = 0; mi < 2; mi++)
        #pragma unroll
        for (int ni = 0; ni < 4; ni++)
            #pragma unroll
            for (int q = 0; q < 4; q++) acc[mi][ni][q] = 0.0f;

    load_tile(0, 0);
    asm volatile("cp.async.wait_group 0;");
    __syncthreads();

    int buf = 0;
    for (int k0 = 0; k0 < K; k0 += BK) {
        const bool has_next = (k0 + BK) < K;
        if (has_next) load_tile(buf ^ 1, k0 + BK);

        #pragma unroll
        for (int ks = 0; ks < 2; ks++) {
            uint32_t a[2][4], b[4][2];
            const int arow = wm + (lane & 15);
            const int acol = ks * 16 + (lane >> 4) * 8;
            #pragma unroll
            for (int mi = 0; mi < 2; mi++)
                ldmA(s2u(&As[buf][(arow + mi * 16) * LDA + acol]),
                     a[mi][0], a[mi][1], a[mi][2], a[mi][3]);
            const int brow = ks * 16 + (lane & 7) + ((lane >> 3) & 1) * 8;
            #pragma unroll
            for (int ni = 0; ni < 4; ni++)
                ldmBT(s2u(&Bs[buf][brow * LDB + wn + ni * 8]), b[ni][0], b[ni][1]);
            #pragma unroll
            for (int mi = 0; mi < 2; mi++)
                #pragma unroll
                for (int ni = 0; ni < 4; ni++)
                    mma16816(acc[mi][ni], a[mi][0], a[mi][1], a[mi][2], a[mi][3],
                             b[ni][0], b[ni][1]);
        }

        if (has_next) {
            asm volatile("cp.async.wait_group 0;");
            __syncthreads();
            buf ^= 1;
        }
    }

    #pragma unroll
    for (int mi = 0; mi < 2; mi++) {
        const int r0 = bm + wm + mi * 16 + (lane >> 2);
        #pragma unroll
        for (int ni = 0; ni < 4; ni++) {
            const int c = bn + wn + ni * 8 + (lane & 3) * 2;
            float x0 = acc[mi][ni][0], x1 = acc[mi][ni][1];
            float x2 = acc[mi][ni][2], x3 = acc[mi][ni][3];
            if (EPI_TANH) {
                const float bv0 = bias[c], bv1 = bias[c + 1];
                x0 = tanhf_(x0 + bv0); x1 = tanhf_(x1 + bv1);
                x2 = tanhf_(x2 + bv0); x3 = tanhf_(x3 + bv1);
            }
            *(__half2*)(C + (size_t)r0 * N + c)       = __floats2half2_rn(x0, x1);
            *(__half2*)(C + (size_t)(r0 + 8) * N + c) = __floats2half2_rn(x2, x3);
        }
    }
}

// ---------------- GEMM wrappers ----------------
__global__ __launch_bounds__(256) void gemm1_k(const float* __restrict__ b1)
{   hgemm_body<1>(g_S, g_W1h, b1, g_H1, BATCH, HIDDEN, DIM); }
__global__ __launch_bounds__(256) void gemm2_k(const float* __restrict__ b2)
{   hgemm_body<1>(g_H1, g_W2h, b2, g_H2, BATCH, HIDDEN / 2, HIDDEN); }
__global__ __launch_bounds__(256) void gemm3_k(const float* __restrict__ b3)
{   hgemm_body<1>(g_H2, g_W3h, b3, g_H3, BATCH, HIDDEN / 4, HIDDEN / 2); }

// ---------------- final: out = sigmoid(H3 . W4 + b4), one warp per row --------
__global__ __launch_bounds__(256) void out_kernel(const float* __restrict__ W4,
                           const float* __restrict__ b4,
                           float* __restrict__ out)
{
    int warp = threadIdx.x >> 5, lane = threadIdx.x & 31;
    int r = blockIdx.x * (blockDim.x >> 5) + warp;
    const __half2* h2 = (const __half2*)(g_H3 + (size_t)r * 128 + lane * 4);
    float2 ha = __half22float2(h2[0]);
    float2 hb = __half22float2(h2[1]);
    const float4 w = *(const float4*)(W4 + lane * 4);
    float s = ha.x * w.x + ha.y * w.y + hb.x * w.z + hb.y * w.w;
    #pragma unroll
    for (int o = 16; o > 0; o >>= 1) s += __shfl_xor_sync(0xFFFFFFFFu, s, o);
    if (lane == 0) out[r] = sigmoidf_(s + b4[0]);
}

// ---------------- launch ----------------
extern "C" void kernel_launch(void* const* d_in, const int* in_sizes, int n_in,
                              void* d_out, int out_size)
{
    const float* z       = (const float*)d_in[0];
    const int*   sid     = (const int*)  d_in[1];
    const int*   eid     = (const int*)  d_in[2];
    const float* kp      = (const float*)d_in[3];
    const float* w_stat  = (const float*)d_in[4];
    const float* b_stat  = (const float*)d_in[5];
    const float* w_kdiff = (const float*)d_in[6];
    const float* b_kdiff = (const float*)d_in[7];
    const float* W1      = (const float*)d_in[8];
    const float* b1      = (const float*)d_in[9];
    const float* W2      = (const float*)d_in[10];
    const float* b2      = (const float*)d_in[11];
    const float* W3      = (const float*)d_in[12];
    const float* b3      = (const float*)d_in[13];
    const float* W4      = (const float*)d_in[14];
    const float* b4      = (const float*)d_in[15];
    float* out = (float*)d_out;

    head_k<<<dim3(2, BATCH / 128), 256>>>(z, sid, eid, w_stat, w_kdiff, kp, b_stat, b_kdiff);
    prep_weights<<<57344 / 256, 256>>>(W1, W2, W3);
    gemm1_k<<<dim3(HIDDEN / 64, BATCH / 128), 256>>>(b1);
    gemm2_k<<<dim3((HIDDEN / 2) / 64, BATCH / 128), 256>>>(b2);
    gemm3_k<<<dim3((HIDDEN / 4) / 64, BATCH / 128), 256>>>(b3);
    out_kernel<<<BATCH / 8, 256>>>(W4, b4, out);
}